// round 15
// baseline (speedup 1.0000x reference)
#include <cuda_runtime.h>
#include <cstdint>
#include <cstddef>

#define LC_    512
#define TSTEPS 256
#define NBLK   128
#define NTHR   608
#define NW     600
#define XT     32
#define PJT    8

typedef unsigned long long u64;

__device__ float g_WcP   [16*300*4];
__device__ float g_WhhP2 [2*13*300*4];
__device__ float g_WdP2  [2*13*300*4];
__device__ float g_Wrz2  [2*13*200*4];
__device__ float g_Wnd   [2*13*100*4];
__device__ float g_WprojP[25*64*4];
__device__ float g_Wc    [300*64];
__device__ float g_bc    [300];
__device__ float g_bd    [300];
__device__ float g_brz   [200];
__device__ float g_xp    [128u*512*300*4];
__device__ float g_hd    [128u*257*4*104];

__global__ void prep1(const float* __restrict__ W_embed,
                      const float* __restrict__ b_embed,
                      const float* __restrict__ W_ih,
                      const float* __restrict__ b_ih,
                      const float* __restrict__ W_hh,
                      const float* __restrict__ W_proj) {
  int idx = blockIdx.x * 256 + threadIdx.x;
  if (idx < 19200) {
    int g = idx >> 6, j = idx & 63;
    float acc = 0.f;
    #pragma unroll 4
    for (int k = 0; k < 100; k++) acc += W_ih[g*100+k] * W_embed[k*64+j];
    g_WcP[(j>>2)*1200 + g*4 + (j&3)] = acc;
    g_Wc[g*64 + j] = acc;
  } else if (idx < 50400) {
    int i2 = idx - 19200, kh = i2 / 300, g = i2 % 300;
    int hf = kh / 52, rem = kh % 52, i = rem >> 2, kk = rem & 3;
    g_WhhP2[((hf*13 + i)*300 + g)*4 + kk] = (kh < 100) ? W_hh[g*100 + kh] : 0.f;
  } else if (idx < 56800) {
    int i2 = idx - 50400, o = i2 / 100, k = i2 % 100;
    g_WprojP[(k>>2)*256 + o*4 + (k&3)] = W_proj[o*100+k];
  } else if (idx < 57100) {
    int g = idx - 56800;
    float acc = b_ih[g];
    for (int k = 0; k < 100; k++) acc += W_ih[g*100+k] * b_embed[k];
    g_bc[g] = acc;
  }
}

__global__ void prep2(const float* __restrict__ W_proj,
                      const float* __restrict__ b_proj) {
  int idx = blockIdx.x * 256 + threadIdx.x;
  if (idx < 31200) {
    int kh = idx / 300, g = idx % 300;
    int hf = kh / 52, rem = kh % 52, i = rem >> 2, kk = rem & 3;
    float acc = 0.f;
    if (kh < 100) {
      #pragma unroll 4
      for (int j = 0; j < 64; j++) acc += g_Wc[g*64+j] * W_proj[j*100 + kh];
    }
    g_WdP2[((hf*13 + i)*300 + g)*4 + kk] = acc;
  } else if (idx < 31500) {
    int g = idx - 31200;
    float acc = g_bc[g];
    #pragma unroll 4
    for (int j = 0; j < 64; j++) acc += g_Wc[g*64+j] * b_proj[j];
    g_bd[g] = acc;
  }
}

__global__ void prep3(const float* __restrict__ b_hh) {
  int idx = blockIdx.x * 256 + threadIdx.x;
  if (idx < 20800) {
    int u = idx >> 2, kk = idx & 3;
    int q = u % 200, w = u / 200;
    g_Wrz2[idx] = g_WhhP2[(w*300 + q)*4 + kk] + g_WdP2[(w*300 + q)*4 + kk];
  } else if (idx < 31200) {
    int i2 = idx - 20800;
    int u = i2 >> 2, kk = i2 & 3;
    int m = u % 100, w = u / 100;
    g_Wnd[i2] = g_WdP2[(w*300 + 200 + m)*4 + kk];
  } else if (idx < 31400) {
    int q = idx - 31200;
    g_brz[q] = b_hh[q] + g_bd[q];
  }
}

__device__ __forceinline__ u64 pk2(float a, float b) {
  u64 r; asm("mov.b64 %0, {%1, %2};" : "=l"(r) : "f"(a), "f"(b)); return r;
}
__device__ __forceinline__ void fma2(u64& d, u64 a, u64 b) {
  asm("fma.rn.f32x2 %0, %1, %2, %0;" : "+l"(d) : "l"(a), "l"(b));
}
__device__ __forceinline__ float2 unpk2(u64 a) {
  float2 f; asm("mov.b64 {%0, %1}, %2;" : "=f"(f.x), "=f"(f.y) : "l"(a)); return f;
}
__device__ __forceinline__ float sigmf(float x) {
  return __fdividef(1.f, 1.f + __expf(-x));
}
__device__ __forceinline__ float tanh_fast(float x) {
  return __fdividef(2.f, 1.f + __expf(-2.f * x)) - 1.f;
}

// batch GEMM xp = ctx @ Wc^T + bc; 4-way t-interleave for ILP (16 accum chains)
__global__ void xprep(const float* __restrict__ ctx,
                      const int*   __restrict__ lens) {
  __shared__ float cS[XT*4*64];          // 32 KB
  const int tid = threadIdx.x;
  const int cta = blockIdx.x, t0 = blockIdx.y * XT;
  const int b0 = cta * 4;
  int maxlen = max(max(lens[b0], lens[b0+1]), max(lens[b0+2], lens[b0+3]));
  if (maxlen > LC_) maxlen = LC_;
  if (t0 >= maxlen) return;              // uniform across block: safe
  for (int i = tid; i < XT*4*16; i += 320) {
    int t = i >> 6, e = (i >> 4) & 3, j4 = i & 15;
    reinterpret_cast<float4*>(cS)[(t*4+e)*16 + j4] =
      reinterpret_cast<const float4*>(ctx)[((size_t)(b0+e)*LC_ + t0 + t)*16 + j4];
  }
  __syncthreads();
  if (tid < 300) {
    u64 wc2[32];
    const ulonglong2* Wc2 = reinterpret_cast<const ulonglong2*>(g_WcP);
    #pragma unroll
    for (int jb = 0; jb < 16; jb++) {
      ulonglong2 w = Wc2[jb*300 + tid];
      wc2[2*jb] = w.x; wc2[2*jb+1] = w.y;
    }
    const float bc = g_bc[tid];
    float4* xpG = reinterpret_cast<float4*>(g_xp);
    const ulonglong2* cb = reinterpret_cast<const ulonglong2*>(cS);
    for (int tg = 0; tg < XT; tg += 4) {
      u64 acc[16];
      const u64 ainit = pk2(bc, 0.f);
      #pragma unroll
      for (int q = 0; q < 16; q++) acc[q] = ainit;
      #pragma unroll
      for (int j4 = 0; j4 < 16; j4++) {
        u64 w0 = wc2[2*j4], w1 = wc2[2*j4+1];
        #pragma unroll
        for (int tt = 0; tt < 4; tt++) {
          const ulonglong2* cbt = cb + (tg + tt)*64;
          ulonglong2 v0 = cbt[0*16 + j4];
          ulonglong2 v1 = cbt[1*16 + j4];
          ulonglong2 v2 = cbt[2*16 + j4];
          ulonglong2 v3 = cbt[3*16 + j4];
          fma2(acc[tt*4+0], w0, v0.x); fma2(acc[tt*4+0], w1, v0.y);
          fma2(acc[tt*4+1], w0, v1.x); fma2(acc[tt*4+1], w1, v1.y);
          fma2(acc[tt*4+2], w0, v2.x); fma2(acc[tt*4+2], w1, v2.y);
          fma2(acc[tt*4+3], w0, v3.x); fma2(acc[tt*4+3], w1, v3.y);
        }
      }
      #pragma unroll
      for (int tt = 0; tt < 4; tt++) {
        float2 s0 = unpk2(acc[tt*4+0]), s1 = unpk2(acc[tt*4+1]);
        float2 s2 = unpk2(acc[tt*4+2]), s3 = unpk2(acc[tt*4+3]);
        xpG[((size_t)cta*LC_ + t0 + tg + tt)*300 + tid] =
          make_float4(s0.x+s0.y, s1.x+s1.y, s2.x+s2.y, s3.x+s3.y);
      }
    }
  }
}

__global__ void projk(const float* __restrict__ bproj_g,
                      float* __restrict__ out) {
  __shared__ float wS[25*64*4];
  const int cta = blockIdx.x, t0 = blockIdx.y * PJT;
  const int tid = threadIdx.x;
  for (int i = tid; i < 1600; i += 256)
    reinterpret_cast<float4*>(wS)[i] = reinterpret_cast<const float4*>(g_WprojP)[i];
  __syncthreads();
  const int e = tid >> 6, o = tid & 63;
  const float bp = __ldg(&bproj_g[o]);
  const float4* Wp4 = reinterpret_cast<const float4*>(wS);
  for (int tt = 0; tt < PJT; tt++) {
    int t = t0 + tt;
    if (t > TSTEPS) break;
    const float4* h4 = reinterpret_cast<const float4*>(
        g_hd + (((size_t)cta*257 + t)*4 + e)*104);
    float acc = bp;
    #pragma unroll
    for (int kb = 0; kb < 25; kb++) {
      float4 w = Wp4[kb*64 + o];
      float4 hv = __ldg(&h4[kb]);
      acc += w.x*hv.x + w.y*hv.y + w.z*hv.z + w.w*hv.w;
    }
    out[((size_t)(cta*4+e)*(TSTEPS+1) + t)*64 + o] = acc;
  }
}

// smem: WndS[0,41600) ; ghH[41600,51200) ; xpH[51200,60800) ; hT ; len
#define OFF_GHH   41600
#define OFF_XPH   51200
#define OFF_HT    60800
#define OFF_LEN   62464
#define SMEM_SZ   62480

__global__ __launch_bounds__(NTHR, 1)
void rnn_kernel(const float* __restrict__ ctx,
                const int*   __restrict__ lens,
                const float* __restrict__ bhh_g,
                float*       __restrict__ out) {
  extern __shared__ char sm[];
  const int tid = threadIdx.x;
  const int cta = blockIdx.x;
  const int b0  = cta << 2;

  float* ghH  = reinterpret_cast<float*>(sm + OFF_GHH);
  float* xpH  = reinterpret_cast<float*>(sm + OFF_XPH);
  float* hT   = reinterpret_cast<float*>(sm + OFF_HT);
  int*   lenS = reinterpret_cast<int*>(sm + OFF_LEN);
  float4* ghH4 = reinterpret_cast<float4*>(ghH);
  float4* xpH4 = reinterpret_cast<float4*>(xpH);

  { // Wnd (decode ni weights) into smem
    const float4* src = reinterpret_cast<const float4*>(g_Wnd);
    float4* dst = reinterpret_cast<float4*>(sm);
    for (int i = tid; i < 2600; i += NTHR) dst[i] = src[i];
  }
  if (tid < 4) lenS[tid] = lens[b0 + tid];
  for (int i = tid; i < 416; i += NTHR) hT[i] = 0.f;
  __syncthreads();

  const int g    = (tid < NW) ? (tid % 300) : 0;
  const int hf   = (tid < NW) ? (tid / 300) : 0;
  const int hf13 = hf * 13;
  const int lenE = lenS[tid & 3];
  int maxlen = max(max(lenS[0], lenS[1]), max(lenS[2], lenS[3]));
  if (maxlen > LC_) maxlen = LC_;

  float bias_h = 0.f;
  if (tid < NW && hf == 0) bias_h = bhh_g[g];

  u64 wh2[26];
  if (tid < NW) {
    const ulonglong2* Wh2 = reinterpret_cast<const ulonglong2*>(g_WhhP2);
    #pragma unroll
    for (int i = 0; i < 13; i++) {
      ulonglong2 w = Wh2[(hf13 + i)*300 + g];
      wh2[2*i] = w.x; wh2[2*i+1] = w.y;
    }
  }

  const float4* xpG = reinterpret_cast<const float4*>(g_xp);
  float4 xp_reg = make_float4(0.f,0.f,0.f,0.f);
  if (tid < 300 && maxlen > 0)
    xp_reg = xpG[((size_t)cta*LC_ + 0)*300 + tid];

  // ====== ENCODE ======
  for (int t = 0; t < maxlen; t++) {
    if (tid < 300) {
      xpH4[tid] = xp_reg;
      if (t + 1 < maxlen)
        xp_reg = xpG[((size_t)cta*LC_ + t + 1)*300 + tid];
    }
    if (tid < NW) {
      const ulonglong2* h2 = reinterpret_cast<const ulonglong2*>(hT);
      u64 a0 = 0, a1 = 0, a2 = 0, a3 = 0;
      #pragma unroll
      for (int i = 0; i < 13; i++) {
        u64 w0 = wh2[2*i], w1 = wh2[2*i+1];
        ulonglong2 v0 = h2[ 0 + hf13 + i];
        ulonglong2 v1 = h2[26 + hf13 + i];
        ulonglong2 v2 = h2[52 + hf13 + i];
        ulonglong2 v3 = h2[78 + hf13 + i];
        fma2(a0, w0, v0.x); fma2(a0, w1, v0.y);
        fma2(a1, w0, v1.x); fma2(a1, w1, v1.y);
        fma2(a2, w0, v2.x); fma2(a2, w1, v2.y);
        fma2(a3, w0, v3.x); fma2(a3, w1, v3.y);
      }
      float2 s0 = unpk2(a0), s1 = unpk2(a1), s2 = unpk2(a2), s3 = unpk2(a3);
      ghH4[hf*300 + g] =
        make_float4(s0.x+s0.y+bias_h, s1.x+s1.y+bias_h,
                    s2.x+s2.y+bias_h, s3.x+s3.y+bias_h);
    }
    __syncthreads();

    if (tid < 400) {
      const int e = tid & 3, k = tid >> 2, o = k*4 + e;
      float rh = ghH[o]     + ghH[1200+o];
      float zh = ghH[o+400] + ghH[1200+o+400];
      float nh = ghH[o+800] + ghH[1200+o+800];
      float r  = sigmf(xpH[o] + rh);
      float zz = sigmf(xpH[o+400] + zh);
      float n  = tanh_fast(xpH[o+800] + r*nh);
      float hv = hT[e*104 + k];
      if (t < lenE) hT[e*104 + k] = n + zz*(hv - n);
    }
    __syncthreads();
  }

  // snapshot h0
  if (tid < 416) {
    int e = tid / 104, k = tid % 104;
    g_hd[(((size_t)cta*257 + 0)*4 + e)*104 + k] = hT[e*104 + k];
  }

  // ---- decode identities + reg weight reload (one k-half slice each) ----
  int qd = 0, hfd = 0;
  float bias_d1 = 0.f, bias_ni = 0.f;
  if (tid < 400) {
    qd = tid % 200; hfd = tid / 200;
    const ulonglong2* Wrz = reinterpret_cast<const ulonglong2*>(g_Wrz2);
    #pragma unroll
    for (int i = 0; i < 13; i++) {
      ulonglong2 w = Wrz[(hfd*13 + i)*200 + qd];
      wh2[2*i] = w.x; wh2[2*i+1] = w.y;
    }
    if (hfd == 0) bias_d1 = g_brz[qd];
  } else if (tid < NW) {
    qd = (tid - 400) % 100; hfd = (tid - 400) / 100;
    const ulonglong2* Wh2 = reinterpret_cast<const ulonglong2*>(g_WhhP2);
    #pragma unroll
    for (int i = 0; i < 13; i++) {
      ulonglong2 w = Wh2[(hfd*13 + i)*300 + 200 + qd];
      wh2[2*i] = w.x; wh2[2*i+1] = w.y;
    }
    if (hfd == 0) { bias_d1 = bhh_g[200 + qd]; bias_ni = g_bd[200 + qd]; }
  }
  const int hfd13 = hfd * 13;
  const ulonglong2* Wnd2 = reinterpret_cast<const ulonglong2*>(sm);
  __syncthreads();

  // ====== DECODE (merged rz in regs; ni streamed from smem) ======
  for (int tt = 0; tt < TSTEPS; tt++) {
    const ulonglong2* h2 = reinterpret_cast<const ulonglong2*>(hT);
    if (tid < 400) {                        // merged r,z rows
      u64 a0 = 0, a1 = 0, a2 = 0, a3 = 0;
      #pragma unroll
      for (int i = 0; i < 13; i++) {
        u64 w0 = wh2[2*i], w1 = wh2[2*i+1];
        ulonglong2 v0 = h2[ 0 + hfd13 + i];
        ulonglong2 v1 = h2[26 + hfd13 + i];
        ulonglong2 v2 = h2[52 + hfd13 + i];
        ulonglong2 v3 = h2[78 + hfd13 + i];
        fma2(a0, w0, v0.x); fma2(a0, w1, v0.y);
        fma2(a1, w0, v1.x); fma2(a1, w1, v1.y);
        fma2(a2, w0, v2.x); fma2(a2, w1, v2.y);
        fma2(a3, w0, v3.x); fma2(a3, w1, v3.y);
      }
      float2 s0 = unpk2(a0), s1 = unpk2(a1), s2 = unpk2(a2), s3 = unpk2(a3);
      ghH4[hfd*300 + qd] =
        make_float4(s0.x+s0.y+bias_d1, s1.x+s1.y+bias_d1,
                    s2.x+s2.y+bias_d1, s3.x+s3.y+bias_d1);
    } else if (tid < NW) {                  // n rows: nh (regs) + ni (smem)
      u64 g0=0, g1=0, g2=0, g3=0, x0=0, x1=0, x2=0, x3=0;
      #pragma unroll
      for (int i = 0; i < 13; i++) {
        u64 w0 = wh2[2*i], w1 = wh2[2*i+1];
        ulonglong2 wd = Wnd2[(hfd13 + i)*100 + qd];
        ulonglong2 v0 = h2[ 0 + hfd13 + i];
        ulonglong2 v1 = h2[26 + hfd13 + i];
        ulonglong2 v2 = h2[52 + hfd13 + i];
        ulonglong2 v3 = h2[78 + hfd13 + i];
        fma2(g0, w0, v0.x); fma2(g0, w1, v0.y);
        fma2(x0, wd.x, v0.x); fma2(x0, wd.y, v0.y);
        fma2(g1, w0, v1.x); fma2(g1, w1, v1.y);
        fma2(x1, wd.x, v1.x); fma2(x1, wd.y, v1.y);
        fma2(g2, w0, v2.x); fma2(g2, w1, v2.y);
        fma2(x2, wd.x, v2.x); fma2(x2, wd.y, v2.y);
        fma2(g3, w0, v3.x); fma2(g3, w1, v3.y);
        fma2(x3, wd.x, v3.x); fma2(x3, wd.y, v3.y);
      }
      float2 s0 = unpk2(g0), s1 = unpk2(g1), s2 = unpk2(g2), s3 = unpk2(g3);
      ghH4[hfd*300 + 200 + qd] =
        make_float4(s0.x+s0.y+bias_d1, s1.x+s1.y+bias_d1,
                    s2.x+s2.y+bias_d1, s3.x+s3.y+bias_d1);
      float2 q0 = unpk2(x0), q1 = unpk2(x1), q2 = unpk2(x2), q3 = unpk2(x3);
      xpH4[hfd*300 + 200 + qd] =
        make_float4(q0.x+q0.y+bias_ni, q1.x+q1.y+bias_ni,
                    q2.x+q2.y+bias_ni, q3.x+q3.y+bias_ni);
    }
    __syncthreads();

    if (tid < 400) {
      const int e = tid & 3, k = tid >> 2, o = k*4 + e;
      float rp = ghH[o]      + ghH[1200+o];
      float zp = ghH[o+400]  + ghH[1200+o+400];
      float nh = ghH[o+800]  + ghH[1200+o+800];
      float ni = xpH[o+800]  + xpH[1200+o+800];
      float r  = sigmf(rp);
      float zz = sigmf(zp);
      float n  = tanh_fast(ni + r*nh);
      float hv = hT[e*104 + k];
      float hn = n + zz*(hv - n);
      hT[e*104 + k] = hn;
      g_hd[(((size_t)cta*257 + tt + 1)*4 + e)*104 + k] = hn;
    }
    __syncthreads();
  }
}

extern "C" void kernel_launch(void* const* d_in, const int* in_sizes, int n_in,
                              void* d_out, int out_size) {
  int off = 2;
  if (n_in >= 11 && in_sizes[2] == 1) off = 3;
  const float* ctx     = (const float*)d_in[0];
  const int*   lens    = (const int*)  d_in[1];
  const float* W_embed = (const float*)d_in[off+0];
  const float* b_embed = (const float*)d_in[off+1];
  const float *W_ih, *b_ih, *W_hh, *b_hh;
  if (in_sizes[off+3] == 300) {
    W_ih = (const float*)d_in[off+2]; b_ih = (const float*)d_in[off+3];
    W_hh = (const float*)d_in[off+4]; b_hh = (const float*)d_in[off+5];
  } else {
    W_ih = (const float*)d_in[off+2]; W_hh = (const float*)d_in[off+3];
    b_ih = (const float*)d_in[off+4]; b_hh = (const float*)d_in[off+5];
  }
  const float* W_proj = (const float*)d_in[off+6];
  const float* b_proj = (const float*)d_in[off+7];
  float* out = (float*)d_out;

  prep1<<<224, 256>>>(W_embed, b_embed, W_ih, b_ih, W_hh, W_proj);
  prep2<<<124, 256>>>(W_proj, b_proj);
  prep3<<<123, 256>>>(b_hh);
  xprep<<<dim3(128, LC_/XT), 320>>>(ctx, lens);
  cudaFuncSetAttribute(rnn_kernel, cudaFuncAttributeMaxDynamicSharedMemorySize, SMEM_SZ);
  rnn_kernel<<<NBLK, NTHR, SMEM_SZ>>>(ctx, lens, b_hh, out);
  projk<<<dim3(128, (TSTEPS + PJT) / PJT), 256>>>(b_proj, out);
}

// round 16
// speedup vs baseline: 1.0207x; 1.0207x over previous
#include <cuda_runtime.h>
#include <cstdint>
#include <cstddef>

#define LC_    512
#define TSTEPS 256
#define NBLK   128
#define NTHR   608
#define NW     600
#define XT     16
#define PJT    8

typedef unsigned long long u64;

__device__ float g_WcP   [16*300*4];
__device__ float g_WhhP2 [2*13*300*4];
__device__ float g_WdP2  [2*13*300*4];
__device__ float g_Wrz2  [2*13*200*4];
__device__ float g_Wnd   [2*13*100*4];
__device__ float g_WprojP[25*64*4];
__device__ float g_Wc    [300*64];
__device__ float g_bc    [300];
__device__ float g_bd    [300];
__device__ float g_brz   [200];
__device__ float g_xp    [128u*512*300*4];
__device__ float g_hd    [128u*257*4*104];

__global__ void prep1(const float* __restrict__ W_embed,
                      const float* __restrict__ b_embed,
                      const float* __restrict__ W_ih,
                      const float* __restrict__ b_ih,
                      const float* __restrict__ W_hh,
                      const float* __restrict__ W_proj) {
  int idx = blockIdx.x * 256 + threadIdx.x;
  if (idx < 19200) {
    int g = idx >> 6, j = idx & 63;
    float acc = 0.f;
    #pragma unroll 4
    for (int k = 0; k < 100; k++) acc += W_ih[g*100+k] * W_embed[k*64+j];
    g_WcP[(j>>2)*1200 + g*4 + (j&3)] = acc;
    g_Wc[g*64 + j] = acc;
  } else if (idx < 50400) {
    int i2 = idx - 19200, kh = i2 / 300, g = i2 % 300;
    int hf = kh / 52, rem = kh % 52, i = rem >> 2, kk = rem & 3;
    g_WhhP2[((hf*13 + i)*300 + g)*4 + kk] = (kh < 100) ? W_hh[g*100 + kh] : 0.f;
  } else if (idx < 56800) {
    int i2 = idx - 50400, o = i2 / 100, k = i2 % 100;
    g_WprojP[(k>>2)*256 + o*4 + (k&3)] = W_proj[o*100+k];
  } else if (idx < 57100) {
    int g = idx - 56800;
    float acc = b_ih[g];
    for (int k = 0; k < 100; k++) acc += W_ih[g*100+k] * b_embed[k];
    g_bc[g] = acc;
  }
}

__global__ void prep2(const float* __restrict__ W_proj,
                      const float* __restrict__ b_proj) {
  int idx = blockIdx.x * 256 + threadIdx.x;
  if (idx < 31200) {
    int kh = idx / 300, g = idx % 300;
    int hf = kh / 52, rem = kh % 52, i = rem >> 2, kk = rem & 3;
    float acc = 0.f;
    if (kh < 100) {
      #pragma unroll 4
      for (int j = 0; j < 64; j++) acc += g_Wc[g*64+j] * W_proj[j*100 + kh];
    }
    g_WdP2[((hf*13 + i)*300 + g)*4 + kk] = acc;
  } else if (idx < 31500) {
    int g = idx - 31200;
    float acc = g_bc[g];
    #pragma unroll 4
    for (int j = 0; j < 64; j++) acc += g_Wc[g*64+j] * b_proj[j];
    g_bd[g] = acc;
  }
}

__global__ void prep3(const float* __restrict__ b_hh) {
  int idx = blockIdx.x * 256 + threadIdx.x;
  if (idx < 20800) {
    int u = idx >> 2, kk = idx & 3;
    int q = u % 200, w = u / 200;
    g_Wrz2[idx] = g_WhhP2[(w*300 + q)*4 + kk] + g_WdP2[(w*300 + q)*4 + kk];
  } else if (idx < 31200) {
    int i2 = idx - 20800;
    int u = i2 >> 2, kk = i2 & 3;
    int m = u % 100, w = u / 100;
    g_Wnd[i2] = g_WdP2[(w*300 + 200 + m)*4 + kk];
  } else if (idx < 31400) {
    int q = idx - 31200;
    g_brz[q] = b_hh[q] + g_bd[q];
  }
}

__device__ __forceinline__ u64 pk2(float a, float b) {
  u64 r; asm("mov.b64 %0, {%1, %2};" : "=l"(r) : "f"(a), "f"(b)); return r;
}
__device__ __forceinline__ void fma2(u64& d, u64 a, u64 b) {
  asm("fma.rn.f32x2 %0, %1, %2, %0;" : "+l"(d) : "l"(a), "l"(b));
}
__device__ __forceinline__ float2 unpk2(u64 a) {
  float2 f; asm("mov.b64 {%0, %1}, %2;" : "=f"(f.x), "=f"(f.y) : "l"(a)); return f;
}
__device__ __forceinline__ float sigmf(float x) {
  return __fdividef(1.f, 1.f + __expf(-x));
}
__device__ __forceinline__ float tanh_fast(float x) {
  return __fdividef(2.f, 1.f + __expf(-2.f * x)) - 1.f;
}

// batch GEMM xp = ctx @ Wc^T + bc; 2-way t-interleave, 2 blocks/SM pinned
__global__ void __launch_bounds__(320, 2)
xprep(const float* __restrict__ ctx, const int* __restrict__ lens) {
  __shared__ float cS[XT*4*64];          // 16 KB
  const int tid = threadIdx.x;
  const int cta = blockIdx.x, t0 = blockIdx.y * XT;
  const int b0 = cta * 4;
  int maxlen = max(max(lens[b0], lens[b0+1]), max(lens[b0+2], lens[b0+3]));
  if (maxlen > LC_) maxlen = LC_;
  if (t0 >= maxlen) return;              // uniform across block: safe
  for (int i = tid; i < XT*4*16; i += 320) {
    int t = i >> 6, e = (i >> 4) & 3, j4 = i & 15;
    reinterpret_cast<float4*>(cS)[(t*4+e)*16 + j4] =
      reinterpret_cast<const float4*>(ctx)[((size_t)(b0+e)*LC_ + t0 + t)*16 + j4];
  }
  __syncthreads();
  if (tid < 300) {
    u64 wc2[32];
    const ulonglong2* Wc2 = reinterpret_cast<const ulonglong2*>(g_WcP);
    #pragma unroll
    for (int jb = 0; jb < 16; jb++) {
      ulonglong2 w = Wc2[jb*300 + tid];
      wc2[2*jb] = w.x; wc2[2*jb+1] = w.y;
    }
    const float bc = g_bc[tid];
    float4* xpG = reinterpret_cast<float4*>(g_xp);
    const ulonglong2* cb = reinterpret_cast<const ulonglong2*>(cS);
    for (int tg = 0; tg < XT; tg += 2) {
      u64 acc[8];
      const u64 ainit = pk2(bc, 0.f);
      #pragma unroll
      for (int q = 0; q < 8; q++) acc[q] = ainit;
      #pragma unroll
      for (int j4 = 0; j4 < 16; j4++) {
        u64 w0 = wc2[2*j4], w1 = wc2[2*j4+1];
        #pragma unroll
        for (int tt = 0; tt < 2; tt++) {
          const ulonglong2* cbt = cb + (tg + tt)*64;
          ulonglong2 v0 = cbt[0*16 + j4];
          ulonglong2 v1 = cbt[1*16 + j4];
          ulonglong2 v2 = cbt[2*16 + j4];
          ulonglong2 v3 = cbt[3*16 + j4];
          fma2(acc[tt*4+0], w0, v0.x); fma2(acc[tt*4+0], w1, v0.y);
          fma2(acc[tt*4+1], w0, v1.x); fma2(acc[tt*4+1], w1, v1.y);
          fma2(acc[tt*4+2], w0, v2.x); fma2(acc[tt*4+2], w1, v2.y);
          fma2(acc[tt*4+3], w0, v3.x); fma2(acc[tt*4+3], w1, v3.y);
        }
      }
      #pragma unroll
      for (int tt = 0; tt < 2; tt++) {
        float2 s0 = unpk2(acc[tt*4+0]), s1 = unpk2(acc[tt*4+1]);
        float2 s2 = unpk2(acc[tt*4+2]), s3 = unpk2(acc[tt*4+3]);
        xpG[((size_t)cta*LC_ + t0 + tg + tt)*300 + tid] =
          make_float4(s0.x+s0.y, s1.x+s1.y, s2.x+s2.y, s3.x+s3.y);
      }
    }
  }
}

__global__ void projk(const float* __restrict__ bproj_g,
                      float* __restrict__ out) {
  __shared__ float wS[25*64*4];
  const int cta = blockIdx.x, t0 = blockIdx.y * PJT;
  const int tid = threadIdx.x;
  for (int i = tid; i < 1600; i += 256)
    reinterpret_cast<float4*>(wS)[i] = reinterpret_cast<const float4*>(g_WprojP)[i];
  __syncthreads();
  const int e = tid >> 6, o = tid & 63;
  const float bp = __ldg(&bproj_g[o]);
  const float4* Wp4 = reinterpret_cast<const float4*>(wS);
  for (int tt = 0; tt < PJT; tt++) {
    int t = t0 + tt;
    if (t > TSTEPS) break;
    const float4* h4 = reinterpret_cast<const float4*>(
        g_hd + (((size_t)cta*257 + t)*4 + e)*104);
    float acc = bp;
    #pragma unroll
    for (int kb = 0; kb < 25; kb++) {
      float4 w = Wp4[kb*64 + o];
      float4 hv = __ldg(&h4[kb]);
      acc += w.x*hv.x + w.y*hv.y + w.z*hv.z + w.w*hv.w;
    }
    out[((size_t)(cta*4+e)*(TSTEPS+1) + t)*64 + o] = acc;
  }
}

// smem: WndS[0,41600) ; ghH[41600,51200) ; xpH[51200,60800) ; hT ; len
#define OFF_GHH   41600
#define OFF_XPH   51200
#define OFF_HT    60800
#define OFF_LEN   62464
#define SMEM_SZ   62480

__global__ __launch_bounds__(NTHR, 1)
void rnn_kernel(const float* __restrict__ ctx,
                const int*   __restrict__ lens,
                const float* __restrict__ bhh_g,
                float*       __restrict__ out) {
  extern __shared__ char sm[];
  const int tid = threadIdx.x;
  const int cta = blockIdx.x;
  const int b0  = cta << 2;

  float* ghH  = reinterpret_cast<float*>(sm + OFF_GHH);
  float* xpH  = reinterpret_cast<float*>(sm + OFF_XPH);
  float* hT   = reinterpret_cast<float*>(sm + OFF_HT);
  int*   lenS = reinterpret_cast<int*>(sm + OFF_LEN);
  float4* ghH4 = reinterpret_cast<float4*>(ghH);
  float4* xpH4 = reinterpret_cast<float4*>(xpH);

  { // Wnd (decode ni weights) into smem
    const float4* src = reinterpret_cast<const float4*>(g_Wnd);
    float4* dst = reinterpret_cast<float4*>(sm);
    for (int i = tid; i < 2600; i += NTHR) dst[i] = src[i];
  }
  if (tid < 4) lenS[tid] = lens[b0 + tid];
  for (int i = tid; i < 416; i += NTHR) hT[i] = 0.f;
  __syncthreads();

  const int g    = (tid < NW) ? (tid % 300) : 0;
  const int hf   = (tid < NW) ? (tid / 300) : 0;
  const int hf13 = hf * 13;
  const int lenE = lenS[tid & 3];
  int maxlen = max(max(lenS[0], lenS[1]), max(lenS[2], lenS[3]));
  if (maxlen > LC_) maxlen = LC_;

  float bias_h = 0.f;
  if (tid < NW && hf == 0) bias_h = bhh_g[g];

  u64 wh2[26];
  if (tid < NW) {
    const ulonglong2* Wh2 = reinterpret_cast<const ulonglong2*>(g_WhhP2);
    #pragma unroll
    for (int i = 0; i < 13; i++) {
      ulonglong2 w = Wh2[(hf13 + i)*300 + g];
      wh2[2*i] = w.x; wh2[2*i+1] = w.y;
    }
  }

  const float4* xpG = reinterpret_cast<const float4*>(g_xp);
  float4 xp_reg = make_float4(0.f,0.f,0.f,0.f);
  if (tid < 300 && maxlen > 0)
    xp_reg = xpG[((size_t)cta*LC_ + 0)*300 + tid];

  // ====== ENCODE ======
  for (int t = 0; t < maxlen; t++) {
    if (tid < 300) {
      xpH4[tid] = xp_reg;
      if (t + 1 < maxlen)
        xp_reg = xpG[((size_t)cta*LC_ + t + 1)*300 + tid];
    }
    if (tid < NW) {
      const ulonglong2* h2 = reinterpret_cast<const ulonglong2*>(hT);
      u64 a0 = 0, a1 = 0, a2 = 0, a3 = 0;
      #pragma unroll
      for (int i = 0; i < 13; i++) {
        u64 w0 = wh2[2*i], w1 = wh2[2*i+1];
        ulonglong2 v0 = h2[ 0 + hf13 + i];
        ulonglong2 v1 = h2[26 + hf13 + i];
        ulonglong2 v2 = h2[52 + hf13 + i];
        ulonglong2 v3 = h2[78 + hf13 + i];
        fma2(a0, w0, v0.x); fma2(a0, w1, v0.y);
        fma2(a1, w0, v1.x); fma2(a1, w1, v1.y);
        fma2(a2, w0, v2.x); fma2(a2, w1, v2.y);
        fma2(a3, w0, v3.x); fma2(a3, w1, v3.y);
      }
      float2 s0 = unpk2(a0), s1 = unpk2(a1), s2 = unpk2(a2), s3 = unpk2(a3);
      ghH4[hf*300 + g] =
        make_float4(s0.x+s0.y+bias_h, s1.x+s1.y+bias_h,
                    s2.x+s2.y+bias_h, s3.x+s3.y+bias_h);
    }
    __syncthreads();

    if (tid < 400) {
      const int e = tid & 3, k = tid >> 2, o = k*4 + e;
      float rh = ghH[o]     + ghH[1200+o];
      float zh = ghH[o+400] + ghH[1200+o+400];
      float nh = ghH[o+800] + ghH[1200+o+800];
      float r  = sigmf(xpH[o] + rh);
      float zz = sigmf(xpH[o+400] + zh);
      float n  = tanh_fast(xpH[o+800] + r*nh);
      float hv = hT[e*104 + k];
      if (t < lenE) hT[e*104 + k] = n + zz*(hv - n);
    }
    __syncthreads();
  }

  // snapshot h0
  if (tid < 416) {
    int e = tid / 104, k = tid % 104;
    g_hd[(((size_t)cta*257 + 0)*4 + e)*104 + k] = hT[e*104 + k];
  }

  // ---- decode identities + reg weight reload (one k-half slice each) ----
  int qd = 0, hfd = 0;
  float bias_d1 = 0.f, bias_ni = 0.f;
  if (tid < 400) {
    qd = tid % 200; hfd = tid / 200;
    const ulonglong2* Wrz = reinterpret_cast<const ulonglong2*>(g_Wrz2);
    #pragma unroll
    for (int i = 0; i < 13; i++) {
      ulonglong2 w = Wrz[(hfd*13 + i)*200 + qd];
      wh2[2*i] = w.x; wh2[2*i+1] = w.y;
    }
    if (hfd == 0) bias_d1 = g_brz[qd];
  } else if (tid < NW) {
    qd = (tid - 400) % 100; hfd = (tid - 400) / 100;
    const ulonglong2* Wh2 = reinterpret_cast<const ulonglong2*>(g_WhhP2);
    #pragma unroll
    for (int i = 0; i < 13; i++) {
      ulonglong2 w = Wh2[(hfd*13 + i)*300 + 200 + qd];
      wh2[2*i] = w.x; wh2[2*i+1] = w.y;
    }
    if (hfd == 0) { bias_d1 = bhh_g[200 + qd]; bias_ni = g_bd[200 + qd]; }
  }
  const int hfd13 = hfd * 13;
  const ulonglong2* Wnd2 = reinterpret_cast<const ulonglong2*>(sm);
  __syncthreads();

  // ====== DECODE (merged rz in regs; ni streamed from smem) ======
  for (int tt = 0; tt < TSTEPS; tt++) {
    const ulonglong2* h2 = reinterpret_cast<const ulonglong2*>(hT);
    if (tid < 400) {                        // merged r,z rows
      u64 a0 = 0, a1 = 0, a2 = 0, a3 = 0;
      #pragma unroll
      for (int i = 0; i < 13; i++) {
        u64 w0 = wh2[2*i], w1 = wh2[2*i+1];
        ulonglong2 v0 = h2[ 0 + hfd13 + i];
        ulonglong2 v1 = h2[26 + hfd13 + i];
        ulonglong2 v2 = h2[52 + hfd13 + i];
        ulonglong2 v3 = h2[78 + hfd13 + i];
        fma2(a0, w0, v0.x); fma2(a0, w1, v0.y);
        fma2(a1, w0, v1.x); fma2(a1, w1, v1.y);
        fma2(a2, w0, v2.x); fma2(a2, w1, v2.y);
        fma2(a3, w0, v3.x); fma2(a3, w1, v3.y);
      }
      float2 s0 = unpk2(a0), s1 = unpk2(a1), s2 = unpk2(a2), s3 = unpk2(a3);
      ghH4[hfd*300 + qd] =
        make_float4(s0.x+s0.y+bias_d1, s1.x+s1.y+bias_d1,
                    s2.x+s2.y+bias_d1, s3.x+s3.y+bias_d1);
    } else if (tid < NW) {                  // n rows: nh (regs) + ni (smem)
      u64 g0=0, g1=0, g2=0, g3=0, x0=0, x1=0, x2=0, x3=0;
      #pragma unroll
      for (int i = 0; i < 13; i++) {
        u64 w0 = wh2[2*i], w1 = wh2[2*i+1];
        ulonglong2 wd = Wnd2[(hfd13 + i)*100 + qd];
        ulonglong2 v0 = h2[ 0 + hfd13 + i];
        ulonglong2 v1 = h2[26 + hfd13 + i];
        ulonglong2 v2 = h2[52 + hfd13 + i];
        ulonglong2 v3 = h2[78 + hfd13 + i];
        fma2(g0, w0, v0.x); fma2(g0, w1, v0.y);
        fma2(x0, wd.x, v0.x); fma2(x0, wd.y, v0.y);
        fma2(g1, w0, v1.x); fma2(g1, w1, v1.y);
        fma2(x1, wd.x, v1.x); fma2(x1, wd.y, v1.y);
        fma2(g2, w0, v2.x); fma2(g2, w1, v2.y);
        fma2(x2, wd.x, v2.x); fma2(x2, wd.y, v2.y);
        fma2(g3, w0, v3.x); fma2(g3, w1, v3.y);
        fma2(x3, wd.x, v3.x); fma2(x3, wd.y, v3.y);
      }
      float2 s0 = unpk2(g0), s1 = unpk2(g1), s2 = unpk2(g2), s3 = unpk2(g3);
      ghH4[hfd*300 + 200 + qd] =
        make_float4(s0.x+s0.y+bias_d1, s1.x+s1.y+bias_d1,
                    s2.x+s2.y+bias_d1, s3.x+s3.y+bias_d1);
      float2 q0 = unpk2(x0), q1 = unpk2(x1), q2 = unpk2(x2), q3 = unpk2(x3);
      xpH4[hfd*300 + 200 + qd] =
        make_float4(q0.x+q0.y+bias_ni, q1.x+q1.y+bias_ni,
                    q2.x+q2.y+bias_ni, q3.x+q3.y+bias_ni);
    }
    __syncthreads();

    if (tid < 400) {
      const int e = tid & 3, k = tid >> 2, o = k*4 + e;
      float rp = ghH[o]      + ghH[1200+o];
      float zp = ghH[o+400]  + ghH[1200+o+400];
      float nh = ghH[o+800]  + ghH[1200+o+800];
      float ni = xpH[o+800]  + xpH[1200+o+800];
      float r  = sigmf(rp);
      float zz = sigmf(zp);
      float n  = tanh_fast(ni + r*nh);
      float hv = hT[e*104 + k];
      float hn = n + zz*(hv - n);
      hT[e*104 + k] = hn;
      g_hd[(((size_t)cta*257 + tt + 1)*4 + e)*104 + k] = hn;
    }
    __syncthreads();
  }
}

extern "C" void kernel_launch(void* const* d_in, const int* in_sizes, int n_in,
                              void* d_out, int out_size) {
  int off = 2;
  if (n_in >= 11 && in_sizes[2] == 1) off = 3;
  const float* ctx     = (const float*)d_in[0];
  const int*   lens    = (const int*)  d_in[1];
  const float* W_embed = (const float*)d_in[off+0];
  const float* b_embed = (const float*)d_in[off+1];
  const float *W_ih, *b_ih, *W_hh, *b_hh;
  if (in_sizes[off+3] == 300) {
    W_ih = (const float*)d_in[off+2]; b_ih = (const float*)d_in[off+3];
    W_hh = (const float*)d_in[off+4]; b_hh = (const float*)d_in[off+5];
  } else {
    W_ih = (const float*)d_in[off+2]; W_hh = (const float*)d_in[off+3];
    b_ih = (const float*)d_in[off+4]; b_hh = (const float*)d_in[off+5];
  }
  const float* W_proj = (const float*)d_in[off+6];
  const float* b_proj = (const float*)d_in[off+7];
  float* out = (float*)d_out;

  prep1<<<224, 256>>>(W_embed, b_embed, W_ih, b_ih, W_hh, W_proj);
  prep2<<<124, 256>>>(W_proj, b_proj);
  prep3<<<123, 256>>>(b_hh);
  xprep<<<dim3(128, LC_/XT), 320>>>(ctx, lens);
  cudaFuncSetAttribute(rnn_kernel, cudaFuncAttributeMaxDynamicSharedMemorySize, SMEM_SZ);
  rnn_kernel<<<NBLK, NTHR, SMEM_SZ>>>(ctx, lens, b_hh, out);
  projk<<<dim3(128, (TSTEPS + PJT) / PJT), 256>>>(b_proj, out);
}

// round 17
// speedup vs baseline: 1.0863x; 1.0642x over previous
#include <cuda_runtime.h>
#include <cstdint>
#include <cstddef>

#define LC_    512
#define TSTEPS 256
#define NBLK   128
#define NTHR   608
#define NW     600
#define XT     16
#define PJT    8

typedef unsigned long long u64;

__device__ float g_WcP   [16*300*4];
__device__ float g_WhhP2 [2*13*300*4];
__device__ float g_WdP2  [2*13*300*4];
__device__ float g_Wrz2  [2*13*200*4];
__device__ float g_Wnd   [2*13*100*4];
__device__ float g_WprojP[25*64*4];
__device__ float g_Wc    [300*64];
__device__ float g_bc    [300];
__device__ float g_bd    [300];
__device__ float g_brz   [200];
__device__ float g_xp    [128u*512*300*4];
__device__ float g_hd    [128u*257*4*104];

__global__ void prep1(const float* __restrict__ W_embed,
                      const float* __restrict__ b_embed,
                      const float* __restrict__ W_ih,
                      const float* __restrict__ b_ih,
                      const float* __restrict__ W_hh,
                      const float* __restrict__ W_proj) {
  int idx = blockIdx.x * 256 + threadIdx.x;
  if (idx < 19200) {
    int g = idx >> 6, j = idx & 63;
    float acc = 0.f;
    #pragma unroll 4
    for (int k = 0; k < 100; k++) acc += W_ih[g*100+k] * W_embed[k*64+j];
    g_WcP[(j>>2)*1200 + g*4 + (j&3)] = acc;
    g_Wc[g*64 + j] = acc;
  } else if (idx < 50400) {
    int i2 = idx - 19200, kh = i2 / 300, g = i2 % 300;
    int hf = kh / 52, rem = kh % 52, i = rem >> 2, kk = rem & 3;
    g_WhhP2[((hf*13 + i)*300 + g)*4 + kk] = (kh < 100) ? W_hh[g*100 + kh] : 0.f;
  } else if (idx < 56800) {
    int i2 = idx - 50400, o = i2 / 100, k = i2 % 100;
    g_WprojP[(k>>2)*256 + o*4 + (k&3)] = W_proj[o*100+k];
  } else if (idx < 57100) {
    int g = idx - 56800;
    float acc = b_ih[g];
    for (int k = 0; k < 100; k++) acc += W_ih[g*100+k] * b_embed[k];
    g_bc[g] = acc;
  }
}

__global__ void prep2(const float* __restrict__ W_proj,
                      const float* __restrict__ b_proj) {
  int idx = blockIdx.x * 256 + threadIdx.x;
  if (idx < 31200) {
    int kh = idx / 300, g = idx % 300;
    int hf = kh / 52, rem = kh % 52, i = rem >> 2, kk = rem & 3;
    float acc = 0.f;
    if (kh < 100) {
      #pragma unroll 4
      for (int j = 0; j < 64; j++) acc += g_Wc[g*64+j] * W_proj[j*100 + kh];
    }
    g_WdP2[((hf*13 + i)*300 + g)*4 + kk] = acc;
  } else if (idx < 31500) {
    int g = idx - 31200;
    float acc = g_bc[g];
    #pragma unroll 4
    for (int j = 0; j < 64; j++) acc += g_Wc[g*64+j] * b_proj[j];
    g_bd[g] = acc;
  }
}

__global__ void prep3(const float* __restrict__ b_hh) {
  int idx = blockIdx.x * 256 + threadIdx.x;
  if (idx < 20800) {
    int u = idx >> 2, kk = idx & 3;
    int q = u % 200, w = u / 200;
    g_Wrz2[idx] = g_WhhP2[(w*300 + q)*4 + kk] + g_WdP2[(w*300 + q)*4 + kk];
  } else if (idx < 31200) {
    int i2 = idx - 20800;
    int u = i2 >> 2, kk = i2 & 3;
    int m = u % 100, w = u / 100;
    g_Wnd[i2] = g_WdP2[(w*300 + 200 + m)*4 + kk];
  } else if (idx < 31400) {
    int q = idx - 31200;
    g_brz[q] = b_hh[q] + g_bd[q];
  }
}

__device__ __forceinline__ u64 pk2(float a, float b) {
  u64 r; asm("mov.b64 %0, {%1, %2};" : "=l"(r) : "f"(a), "f"(b)); return r;
}
__device__ __forceinline__ void fma2(u64& d, u64 a, u64 b) {
  asm("fma.rn.f32x2 %0, %1, %2, %0;" : "+l"(d) : "l"(a), "l"(b));
}
__device__ __forceinline__ float2 unpk2(u64 a) {
  float2 f; asm("mov.b64 {%0, %1}, %2;" : "=f"(f.x), "=f"(f.y) : "l"(a)); return f;
}
__device__ __forceinline__ float sigmf(float x) {
  return __fdividef(1.f, 1.f + __expf(-x));
}
__device__ __forceinline__ float tanh_fast(float x) {
  return __fdividef(2.f, 1.f + __expf(-2.f * x)) - 1.f;
}

// batch GEMM xp = ctx @ Wc^T + bc; per-LANE length gating: lane e's dot is
// skipped entirely once t >= len[e] (rnn never reads those slots; h frozen).
__global__ void __launch_bounds__(320, 2)
xprep(const float* __restrict__ ctx, const int* __restrict__ lens) {
  __shared__ float cS[XT*4*64];          // 16 KB
  const int tid = threadIdx.x;
  const int cta = blockIdx.x, t0 = blockIdx.y * XT;
  const int b0 = cta * 4;
  int le[4];
  #pragma unroll
  for (int e = 0; e < 4; e++) le[e] = min(lens[b0 + e], LC_);
  int maxlen = max(max(le[0], le[1]), max(le[2], le[3]));
  if (t0 >= maxlen) return;              // uniform across block: safe
  for (int i = tid; i < XT*4*16; i += 320) {
    int t = i >> 6, e = (i >> 4) & 3, j4 = i & 15;
    reinterpret_cast<float4*>(cS)[(t*4+e)*16 + j4] =
      reinterpret_cast<const float4*>(ctx)[((size_t)(b0+e)*LC_ + t0 + t)*16 + j4];
  }
  __syncthreads();
  if (tid < 300) {
    u64 wc2[32];
    const ulonglong2* Wc2 = reinterpret_cast<const ulonglong2*>(g_WcP);
    #pragma unroll
    for (int jb = 0; jb < 16; jb++) {
      ulonglong2 w = Wc2[jb*300 + tid];
      wc2[2*jb] = w.x; wc2[2*jb+1] = w.y;
    }
    const float bc = g_bc[tid];
    const ulonglong2* cb = reinterpret_cast<const ulonglong2*>(cS);
    const int tmax = min(XT, maxlen - t0);
    for (int t = 0; t < tmax; t++) {
      const int tcur = t0 + t;
      float* dst = g_xp + (((size_t)cta*LC_ + tcur)*300 + tid)*4;
      #pragma unroll
      for (int e = 0; e < 4; e++) {
        if (le[e] > tcur) {                // uniform per block: no divergence
          const ulonglong2* cbe = cb + (t*4 + e)*16;
          u64 aA = pk2(bc, 0.f), aB = 0, aC = 0, aD = 0;
          #pragma unroll
          for (int j4 = 0; j4 < 16; j4 += 2) {
            ulonglong2 v0 = cbe[j4];
            ulonglong2 v1 = cbe[j4+1];
            fma2(aA, wc2[2*j4],   v0.x); fma2(aB, wc2[2*j4+1], v0.y);
            fma2(aC, wc2[2*j4+2], v1.x); fma2(aD, wc2[2*j4+3], v1.y);
          }
          float2 sA = unpk2(aA), sB = unpk2(aB), sC = unpk2(aC), sD = unpk2(aD);
          dst[e] = sA.x + sA.y + sB.x + sB.y + sC.x + sC.y + sD.x + sD.y;
        }
      }
    }
  }
}

__global__ void projk(const float* __restrict__ bproj_g,
                      float* __restrict__ out) {
  __shared__ float wS[25*64*4];
  const int cta = blockIdx.x, t0 = blockIdx.y * PJT;
  const int tid = threadIdx.x;
  for (int i = tid; i < 1600; i += 256)
    reinterpret_cast<float4*>(wS)[i] = reinterpret_cast<const float4*>(g_WprojP)[i];
  __syncthreads();
  const int e = tid >> 6, o = tid & 63;
  const float bp = __ldg(&bproj_g[o]);
  const float4* Wp4 = reinterpret_cast<const float4*>(wS);
  for (int tt = 0; tt < PJT; tt++) {
    int t = t0 + tt;
    if (t > TSTEPS) break;
    const float4* h4 = reinterpret_cast<const float4*>(
        g_hd + (((size_t)cta*257 + t)*4 + e)*104);
    float acc = bp;
    #pragma unroll
    for (int kb = 0; kb < 25; kb++) {
      float4 w = Wp4[kb*64 + o];
      float4 hv = __ldg(&h4[kb]);
      acc += w.x*hv.x + w.y*hv.y + w.z*hv.z + w.w*hv.w;
    }
    out[((size_t)(cta*4+e)*(TSTEPS+1) + t)*64 + o] = acc;
  }
}

// smem: WndS[0,41600) ; ghH[41600,51200) ; xpH[51200,60800) ; hT ; len
#define OFF_GHH   41600
#define OFF_XPH   51200
#define OFF_HT    60800
#define OFF_LEN   62464
#define SMEM_SZ   62480

__global__ __launch_bounds__(NTHR, 1)
void rnn_kernel(const float* __restrict__ ctx,
                const int*   __restrict__ lens,
                const float* __restrict__ bhh_g,
                float*       __restrict__ out) {
  extern __shared__ char sm[];
  const int tid = threadIdx.x;
  const int cta = blockIdx.x;
  const int b0  = cta << 2;

  float* ghH  = reinterpret_cast<float*>(sm + OFF_GHH);
  float* xpH  = reinterpret_cast<float*>(sm + OFF_XPH);
  float* hT   = reinterpret_cast<float*>(sm + OFF_HT);
  int*   lenS = reinterpret_cast<int*>(sm + OFF_LEN);
  float4* ghH4 = reinterpret_cast<float4*>(ghH);
  float4* xpH4 = reinterpret_cast<float4*>(xpH);

  { // Wnd (decode ni weights) into smem
    const float4* src = reinterpret_cast<const float4*>(g_Wnd);
    float4* dst = reinterpret_cast<float4*>(sm);
    for (int i = tid; i < 2600; i += NTHR) dst[i] = src[i];
  }
  if (tid < 4) lenS[tid] = lens[b0 + tid];
  for (int i = tid; i < 416; i += NTHR) hT[i] = 0.f;
  __syncthreads();

  const int g    = (tid < NW) ? (tid % 300) : 0;
  const int hf   = (tid < NW) ? (tid / 300) : 0;
  const int hf13 = hf * 13;
  const int lenE = lenS[tid & 3];
  int maxlen = max(max(lenS[0], lenS[1]), max(lenS[2], lenS[3]));
  if (maxlen > LC_) maxlen = LC_;

  float bias_h = 0.f;
  if (tid < NW && hf == 0) bias_h = bhh_g[g];

  u64 wh2[26];
  if (tid < NW) {
    const ulonglong2* Wh2 = reinterpret_cast<const ulonglong2*>(g_WhhP2);
    #pragma unroll
    for (int i = 0; i < 13; i++) {
      ulonglong2 w = Wh2[(hf13 + i)*300 + g];
      wh2[2*i] = w.x; wh2[2*i+1] = w.y;
    }
  }

  const float4* xpG = reinterpret_cast<const float4*>(g_xp);
  float4 xp_reg = make_float4(0.f,0.f,0.f,0.f);
  if (tid < 300 && maxlen > 0)
    xp_reg = xpG[((size_t)cta*LC_ + 0)*300 + tid];

  // ====== ENCODE ======
  for (int t = 0; t < maxlen; t++) {
    if (tid < 300) {
      xpH4[tid] = xp_reg;
      if (t + 1 < maxlen)
        xp_reg = xpG[((size_t)cta*LC_ + t + 1)*300 + tid];
    }
    if (tid < NW) {
      const ulonglong2* h2 = reinterpret_cast<const ulonglong2*>(hT);
      u64 a0 = 0, a1 = 0, a2 = 0, a3 = 0;
      #pragma unroll
      for (int i = 0; i < 13; i++) {
        u64 w0 = wh2[2*i], w1 = wh2[2*i+1];
        ulonglong2 v0 = h2[ 0 + hf13 + i];
        ulonglong2 v1 = h2[26 + hf13 + i];
        ulonglong2 v2 = h2[52 + hf13 + i];
        ulonglong2 v3 = h2[78 + hf13 + i];
        fma2(a0, w0, v0.x); fma2(a0, w1, v0.y);
        fma2(a1, w0, v1.x); fma2(a1, w1, v1.y);
        fma2(a2, w0, v2.x); fma2(a2, w1, v2.y);
        fma2(a3, w0, v3.x); fma2(a3, w1, v3.y);
      }
      float2 s0 = unpk2(a0), s1 = unpk2(a1), s2 = unpk2(a2), s3 = unpk2(a3);
      ghH4[hf*300 + g] =
        make_float4(s0.x+s0.y+bias_h, s1.x+s1.y+bias_h,
                    s2.x+s2.y+bias_h, s3.x+s3.y+bias_h);
    }
    __syncthreads();

    if (tid < 400) {
      const int e = tid & 3, k = tid >> 2, o = k*4 + e;
      float rh = ghH[o]     + ghH[1200+o];
      float zh = ghH[o+400] + ghH[1200+o+400];
      float nh = ghH[o+800] + ghH[1200+o+800];
      float r  = sigmf(xpH[o] + rh);
      float zz = sigmf(xpH[o+400] + zh);
      float n  = tanh_fast(xpH[o+800] + r*nh);
      float hv = hT[e*104 + k];
      if (t < lenE) hT[e*104 + k] = n + zz*(hv - n);
    }
    __syncthreads();
  }

  // snapshot h0
  if (tid < 416) {
    int e = tid / 104, k = tid % 104;
    g_hd[(((size_t)cta*257 + 0)*4 + e)*104 + k] = hT[e*104 + k];
  }

  // ---- decode identities + reg weight reload (one k-half slice each) ----
  int qd = 0, hfd = 0;
  float bias_d1 = 0.f, bias_ni = 0.f;
  if (tid < 400) {
    qd = tid % 200; hfd = tid / 200;
    const ulonglong2* Wrz = reinterpret_cast<const ulonglong2*>(g_Wrz2);
    #pragma unroll
    for (int i = 0; i < 13; i++) {
      ulonglong2 w = Wrz[(hfd*13 + i)*200 + qd];
      wh2[2*i] = w.x; wh2[2*i+1] = w.y;
    }
    if (hfd == 0) bias_d1 = g_brz[qd];
  } else if (tid < NW) {
    qd = (tid - 400) % 100; hfd = (tid - 400) / 100;
    const ulonglong2* Wh2 = reinterpret_cast<const ulonglong2*>(g_WhhP2);
    #pragma unroll
    for (int i = 0; i < 13; i++) {
      ulonglong2 w = Wh2[(hfd*13 + i)*300 + 200 + qd];
      wh2[2*i] = w.x; wh2[2*i+1] = w.y;
    }
    if (hfd == 0) { bias_d1 = bhh_g[200 + qd]; bias_ni = g_bd[200 + qd]; }
  }
  const int hfd13 = hfd * 13;
  const ulonglong2* Wnd2 = reinterpret_cast<const ulonglong2*>(sm);
  __syncthreads();

  // ====== DECODE (merged rz in regs; ni streamed from smem) ======
  for (int tt = 0; tt < TSTEPS; tt++) {
    const ulonglong2* h2 = reinterpret_cast<const ulonglong2*>(hT);
    if (tid < 400) {                        // merged r,z rows
      u64 a0 = 0, a1 = 0, a2 = 0, a3 = 0;
      #pragma unroll
      for (int i = 0; i < 13; i++) {
        u64 w0 = wh2[2*i], w1 = wh2[2*i+1];
        ulonglong2 v0 = h2[ 0 + hfd13 + i];
        ulonglong2 v1 = h2[26 + hfd13 + i];
        ulonglong2 v2 = h2[52 + hfd13 + i];
        ulonglong2 v3 = h2[78 + hfd13 + i];
        fma2(a0, w0, v0.x); fma2(a0, w1, v0.y);
        fma2(a1, w0, v1.x); fma2(a1, w1, v1.y);
        fma2(a2, w0, v2.x); fma2(a2, w1, v2.y);
        fma2(a3, w0, v3.x); fma2(a3, w1, v3.y);
      }
      float2 s0 = unpk2(a0), s1 = unpk2(a1), s2 = unpk2(a2), s3 = unpk2(a3);
      ghH4[hfd*300 + qd] =
        make_float4(s0.x+s0.y+bias_d1, s1.x+s1.y+bias_d1,
                    s2.x+s2.y+bias_d1, s3.x+s3.y+bias_d1);
    } else if (tid < NW) {                  // n rows: nh (regs) + ni (smem)
      u64 g0=0, g1=0, g2=0, g3=0, x0=0, x1=0, x2=0, x3=0;
      #pragma unroll
      for (int i = 0; i < 13; i++) {
        u64 w0 = wh2[2*i], w1 = wh2[2*i+1];
        ulonglong2 wd = Wnd2[(hfd13 + i)*100 + qd];
        ulonglong2 v0 = h2[ 0 + hfd13 + i];
        ulonglong2 v1 = h2[26 + hfd13 + i];
        ulonglong2 v2 = h2[52 + hfd13 + i];
        ulonglong2 v3 = h2[78 + hfd13 + i];
        fma2(g0, w0, v0.x); fma2(g0, w1, v0.y);
        fma2(x0, wd.x, v0.x); fma2(x0, wd.y, v0.y);
        fma2(g1, w0, v1.x); fma2(g1, w1, v1.y);
        fma2(x1, wd.x, v1.x); fma2(x1, wd.y, v1.y);
        fma2(g2, w0, v2.x); fma2(g2, w1, v2.y);
        fma2(x2, wd.x, v2.x); fma2(x2, wd.y, v2.y);
        fma2(g3, w0, v3.x); fma2(g3, w1, v3.y);
        fma2(x3, wd.x, v3.x); fma2(x3, wd.y, v3.y);
      }
      float2 s0 = unpk2(g0), s1 = unpk2(g1), s2 = unpk2(g2), s3 = unpk2(g3);
      ghH4[hfd*300 + 200 + qd] =
        make_float4(s0.x+s0.y+bias_d1, s1.x+s1.y+bias_d1,
                    s2.x+s2.y+bias_d1, s3.x+s3.y+bias_d1);
      float2 q0 = unpk2(x0), q1 = unpk2(x1), q2 = unpk2(x2), q3 = unpk2(x3);
      xpH4[hfd*300 + 200 + qd] =
        make_float4(q0.x+q0.y+bias_ni, q1.x+q1.y+bias_ni,
                    q2.x+q2.y+bias_ni, q3.x+q3.y+bias_ni);
    }
    __syncthreads();

    if (tid < 400) {
      const int e = tid & 3, k = tid >> 2, o = k*4 + e;
      float rp = ghH[o]      + ghH[1200+o];
      float zp = ghH[o+400]  + ghH[1200+o+400];
      float nh = ghH[o+800]  + ghH[1200+o+800];
      float ni = xpH[o+800]  + xpH[1200+o+800];
      float r  = sigmf(rp);
      float zz = sigmf(zp);
      float n  = tanh_fast(ni + r*nh);
      float hv = hT[e*104 + k];
      float hn = n + zz*(hv - n);
      hT[e*104 + k] = hn;
      g_hd[(((size_t)cta*257 + tt + 1)*4 + e)*104 + k] = hn;
    }
    __syncthreads();
  }
}

extern "C" void kernel_launch(void* const* d_in, const int* in_sizes, int n_in,
                              void* d_out, int out_size) {
  int off = 2;
  if (n_in >= 11 && in_sizes[2] == 1) off = 3;
  const float* ctx     = (const float*)d_in[0];
  const int*   lens    = (const int*)  d_in[1];
  const float* W_embed = (const float*)d_in[off+0];
  const float* b_embed = (const float*)d_in[off+1];
  const float *W_ih, *b_ih, *W_hh, *b_hh;
  if (in_sizes[off+3] == 300) {
    W_ih = (const float*)d_in[off+2]; b_ih = (const float*)d_in[off+3];
    W_hh = (const float*)d_in[off+4]; b_hh = (const float*)d_in[off+5];
  } else {
    W_ih = (const float*)d_in[off+2]; W_hh = (const float*)d_in[off+3];
    b_ih = (const float*)d_in[off+4]; b_hh = (const float*)d_in[off+5];
  }
  const float* W_proj = (const float*)d_in[off+6];
  const float* b_proj = (const float*)d_in[off+7];
  float* out = (float*)d_out;

  prep1<<<224, 256>>>(W_embed, b_embed, W_ih, b_ih, W_hh, W_proj);
  prep2<<<124, 256>>>(W_proj, b_proj);
  prep3<<<123, 256>>>(b_hh);
  xprep<<<dim3(128, LC_/XT), 320>>>(ctx, lens);
  cudaFuncSetAttribute(rnn_kernel, cudaFuncAttributeMaxDynamicSharedMemorySize, SMEM_SZ);
  rnn_kernel<<<NBLK, NTHR, SMEM_SZ>>>(ctx, lens, b_hh, out);
  projk<<<dim3(128, (TSTEPS + PJT) / PJT), 256>>>(b_proj, out);
}